// round 10
// baseline (speedup 1.0000x reference)
#include <cuda_runtime.h>

// TypeAttention reduces algebraically to alpha[e] = 1 / in_degree(dst[e]) per
// relation (per-dst softmax over identical logits = uniform). Output = concat.
//
// Diagonal 3-kernel pipeline on ONE stream, self-cleaning, no memsets:
//   k1: hist_ui (8 REDs/thread — RED issue rate scales with per-thread
//       batching, not occupancy) + zero cnt_iu
//   k2: gather_ui (L1tex-bound, 4/thread) + hist_iu (L2-atomic-bound)
//       — disjoint pipes, measured ~7.3us for 15.4us of serial work
//   k3: gather_iu + zero cnt_ui (readies next replay)
// Static zero-init covers the first call; each replay re-zeros both tables.

#define MAX_NODES 100000
#define TPB 256

__device__ int g_cnt[2 * MAX_NODES];   // [0,N): ui  [N,2N): iu

// k1: histogram relation ui at 8 REDs/thread; also zero cnt_iu.
__global__ void k1_hist_ui_zero_iu(const int* __restrict__ dst_ui, int E, int Nn) {
    int i = blockIdx.x * TPB + threadIdx.x;
    int e8 = E >> 3;
    if (i < e8) {
        int4 a = __ldg((const int4*)dst_ui + 2 * i);
        int4 b = __ldg((const int4*)dst_ui + 2 * i + 1);
        atomicAdd(&g_cnt[a.x], 1);
        atomicAdd(&g_cnt[a.y], 1);
        atomicAdd(&g_cnt[a.z], 1);
        atomicAdd(&g_cnt[a.w], 1);
        atomicAdd(&g_cnt[b.x], 1);
        atomicAdd(&g_cnt[b.y], 1);
        atomicAdd(&g_cnt[b.z], 1);
        atomicAdd(&g_cnt[b.w], 1);
    } else if (i == e8) {
        for (int j = e8 << 3; j < E; j++) atomicAdd(&g_cnt[dst_ui[j]], 1);
    }
    if (i < Nn) g_cnt[MAX_NODES + i] = 0;
}

// k2: gather relation ui (reads final cnt_ui) + histogram relation iu.
__global__ void k2_gather_ui_hist_iu(const int* __restrict__ dst_ui,
                                     const int* __restrict__ dst_iu,
                                     float* __restrict__ out, int E) {
    int i = blockIdx.x * TPB + threadIdx.x;
    int e4 = E >> 2;
    if (i < e4) {
        int4 a = __ldg((const int4*)dst_ui + i);
        int4 b = __ldg((const int4*)dst_iu + i);
        // REDs are fire-and-forget: issue first, they drain under the gather.
        atomicAdd(&g_cnt[MAX_NODES + b.x], 1);
        atomicAdd(&g_cnt[MAX_NODES + b.y], 1);
        atomicAdd(&g_cnt[MAX_NODES + b.z], 1);
        atomicAdd(&g_cnt[MAX_NODES + b.w], 1);
        float4 r;
        r.x = 1.0f / (float)g_cnt[a.x];
        r.y = 1.0f / (float)g_cnt[a.y];
        r.z = 1.0f / (float)g_cnt[a.z];
        r.w = 1.0f / (float)g_cnt[a.w];
        ((float4*)out)[i] = r;
    } else if (i == e4) {
        for (int j = e4 << 2; j < E; j++) {
            atomicAdd(&g_cnt[MAX_NODES + dst_iu[j]], 1);
            out[j] = 1.0f / (float)g_cnt[dst_ui[j]];
        }
    }
}

// k3: gather relation iu; also zero cnt_ui for the next graph replay.
__global__ void k3_gather_iu_zero_ui(const int* __restrict__ dst_iu,
                                     float* __restrict__ out_iu, int E, int Nn) {
    int i = blockIdx.x * TPB + threadIdx.x;
    int e4 = E >> 2;
    if (i < e4) {
        int4 b = __ldg((const int4*)dst_iu + i);
        float4 r;
        r.x = 1.0f / (float)g_cnt[MAX_NODES + b.x];
        r.y = 1.0f / (float)g_cnt[MAX_NODES + b.y];
        r.z = 1.0f / (float)g_cnt[MAX_NODES + b.z];
        r.w = 1.0f / (float)g_cnt[MAX_NODES + b.w];
        ((float4*)out_iu)[i] = r;
    } else if (i == e4) {
        for (int j = e4 << 2; j < E; j++)
            out_iu[j] = 1.0f / (float)g_cnt[MAX_NODES + dst_iu[j]];
    }
    if (i < Nn) g_cnt[i] = 0;
}

extern "C" void kernel_launch(void* const* d_in, const int* in_sizes, int n_in,
                              void* d_out, int out_size) {
    // Inputs: h_user, h_item, Wl_user, bl_user, Wl_item, bl_item,
    //         Wr_user, br_user, Wr_item, br_item, attn_w,
    //         src_ui, dst_ui, src_iu, dst_iu
    const int* dst_ui = (const int*)d_in[12];
    const int* dst_iu = (const int*)d_in[14];
    float* out = (float*)d_out;

    int D  = in_sizes[3];
    int Nn = in_sizes[0] / D;
    if (Nn > MAX_NODES) Nn = MAX_NODES;
    int E = in_sizes[12];

    // k1: 8 edges/thread, must still cover Nn zeroing threads
    int e8_threads = (E >> 3) + 1;
    int t1 = e8_threads > Nn ? e8_threads : Nn;
    int b1 = (t1 + TPB - 1) / TPB;

    // k2/k3: 4 edges/thread (gathers want max warps in flight)
    int e4_threads = (E >> 2) + 1;
    int t3 = e4_threads > Nn ? e4_threads : Nn;
    int b2 = (e4_threads + TPB - 1) / TPB;
    int b3 = (t3 + TPB - 1) / TPB;

    k1_hist_ui_zero_iu<<<b1, TPB>>>(dst_ui, E, Nn);
    k2_gather_ui_hist_iu<<<b2, TPB>>>(dst_ui, dst_iu, out, E);
    k3_gather_iu_zero_ui<<<b3, TPB>>>(dst_iu, out + E, E, Nn);
}

// round 11
// speedup vs baseline: 1.0782x; 1.0782x over previous
#include <cuda_runtime.h>

// TypeAttention reduces algebraically to alpha[e] = 1 / in_degree(dst[e]) per
// relation (per-dst softmax over identical logits = uniform). Output = concat.
//
// Diagonal 3-kernel pipeline with PDL overlap. Fixed per-kernel cost c~4us
// (ramp+drain) dominates the schedule; PDL lets kernel N+1 preload its index
// vectors into registers while kernel N drains, then gridDependencySync
// before touching the count tables.
//   k1: [pre: ld dst_ui] sync; hist_ui REDs + zero cnt_iu
//   k2: [pre: ld dst_ui,dst_iu] sync; hist_iu REDs + gather_ui  (disjoint pipes)
//   k3: [pre: ld dst_iu] sync; gather_iu + zero cnt_ui (next replay)
// Static zero-init covers call #1; each replay leaves both tables zeroed.

#define MAX_NODES 100000
#define TPB 256

__device__ int g_cnt[2 * MAX_NODES];   // [0,N): ui  [N,2N): iu

__global__ void k1_hist_ui_zero_iu(const int* __restrict__ dst_ui, int E, int Nn) {
    int i = blockIdx.x * TPB + threadIdx.x;
    int e4 = E >> 2;
    int4 a;
    bool act = i < e4;
    if (act) a = __ldg((const int4*)dst_ui + i);      // prelude: input-only
    cudaGridDependencySynchronize();                  // wait prior k3 (zero_ui)
    if (act) {
        atomicAdd(&g_cnt[a.x], 1);
        atomicAdd(&g_cnt[a.y], 1);
        atomicAdd(&g_cnt[a.z], 1);
        atomicAdd(&g_cnt[a.w], 1);
    } else if (i == e4) {
        for (int j = e4 << 2; j < E; j++) atomicAdd(&g_cnt[dst_ui[j]], 1);
    }
    if (i < Nn) g_cnt[MAX_NODES + i] = 0;
    cudaTriggerProgrammaticLaunchCompletion();
}

__global__ void k2_gather_ui_hist_iu(const int* __restrict__ dst_ui,
                                     const int* __restrict__ dst_iu,
                                     float* __restrict__ out, int E) {
    int i = blockIdx.x * TPB + threadIdx.x;
    int e4 = E >> 2;
    int4 a, b;
    bool act = i < e4;
    if (act) {
        a = __ldg((const int4*)dst_ui + i);           // prelude: input-only
        b = __ldg((const int4*)dst_iu + i);
    }
    cudaGridDependencySynchronize();                  // k1 complete & visible
    if (act) {
        // fire-and-forget REDs drain under the gather (different pipes)
        atomicAdd(&g_cnt[MAX_NODES + b.x], 1);
        atomicAdd(&g_cnt[MAX_NODES + b.y], 1);
        atomicAdd(&g_cnt[MAX_NODES + b.z], 1);
        atomicAdd(&g_cnt[MAX_NODES + b.w], 1);
        float4 r;
        r.x = 1.0f / (float)g_cnt[a.x];
        r.y = 1.0f / (float)g_cnt[a.y];
        r.z = 1.0f / (float)g_cnt[a.z];
        r.w = 1.0f / (float)g_cnt[a.w];
        ((float4*)out)[i] = r;
    } else if (i == e4) {
        for (int j = e4 << 2; j < E; j++) {
            atomicAdd(&g_cnt[MAX_NODES + dst_iu[j]], 1);
            out[j] = 1.0f / (float)g_cnt[dst_ui[j]];
        }
    }
    cudaTriggerProgrammaticLaunchCompletion();
}

__global__ void k3_gather_iu_zero_ui(const int* __restrict__ dst_iu,
                                     float* __restrict__ out_iu, int E, int Nn) {
    int i = blockIdx.x * TPB + threadIdx.x;
    int e4 = E >> 2;
    int4 b;
    bool act = i < e4;
    if (act) b = __ldg((const int4*)dst_iu + i);      // prelude: input-only
    cudaGridDependencySynchronize();                  // k2 complete & visible
    if (act) {
        float4 r;
        r.x = 1.0f / (float)g_cnt[MAX_NODES + b.x];
        r.y = 1.0f / (float)g_cnt[MAX_NODES + b.y];
        r.z = 1.0f / (float)g_cnt[MAX_NODES + b.z];
        r.w = 1.0f / (float)g_cnt[MAX_NODES + b.w];
        ((float4*)out_iu)[i] = r;
    } else if (i == e4) {
        for (int j = e4 << 2; j < E; j++)
            out_iu[j] = 1.0f / (float)g_cnt[MAX_NODES + dst_iu[j]];
    }
    if (i < Nn) g_cnt[i] = 0;                         // ready next replay's k1
    cudaTriggerProgrammaticLaunchCompletion();
}

extern "C" void kernel_launch(void* const* d_in, const int* in_sizes, int n_in,
                              void* d_out, int out_size) {
    // Inputs: h_user, h_item, Wl_user, bl_user, Wl_item, bl_item,
    //         Wr_user, br_user, Wr_item, br_item, attn_w,
    //         src_ui, dst_ui, src_iu, dst_iu
    const int* dst_ui = (const int*)d_in[12];
    const int* dst_iu = (const int*)d_in[14];
    float* out = (float*)d_out;

    int D  = in_sizes[3];
    int Nn = in_sizes[0] / D;
    if (Nn > MAX_NODES) Nn = MAX_NODES;
    int E = in_sizes[12];

    int e4_threads = (E >> 2) + 1;                       // +1 for tail
    int nthreads = e4_threads > Nn ? e4_threads : Nn;    // cover zeroing too
    unsigned eb = (nthreads + TPB - 1) / TPB;

    cudaLaunchAttribute attr[1];
    attr[0].id = cudaLaunchAttributeProgrammaticStreamSerialization;
    attr[0].val.programmaticStreamSerializationAllowed = 1;

    cudaLaunchConfig_t cfg = {};
    cfg.gridDim  = {eb, 1, 1};
    cfg.blockDim = {TPB, 1, 1};
    cfg.dynamicSmemBytes = 0;
    cfg.stream = 0;               // legacy default (the capture stream)
    cfg.attrs = attr;
    cfg.numAttrs = 1;

    cudaLaunchKernelEx(&cfg, k1_hist_ui_zero_iu, dst_ui, E, Nn);
    cudaLaunchKernelEx(&cfg, k2_gather_ui_hist_iu, dst_ui, dst_iu, out, E);
    cudaLaunchKernelEx(&cfg, k3_gather_iu_zero_ui, dst_iu, (float*)(out + E), E, Nn);
}